// round 7
// baseline (speedup 1.0000x reference)
#include <cuda_runtime.h>
#include <cuda_fp16.h>
#include <cstdint>

#define DM 512
#define NH 8
#define DK 64
#define BB 4
#define LL 2048
#define MROWS (BB*LL)                    // 8192
#define OUT_ELEMS ((size_t)MROWS*DM)     // 4,194,304
#define NROWS (BB*NH*LL)                 // 65536 softmax rows
#define NCT 32                           // 2048 / 64-wide stat tiles

__device__ __half g_Qh[MROWS*DM];   // Q * 0.125 in fp16
__device__ __half g_Kh[MROWS*DM];
__device__ __half g_Vh[MROWS*DM];
__device__ float g_mpart[(size_t)NROWS*NCT];
__device__ float g_spart[(size_t)NROWS*NCT];
__device__ float g_rowm[NROWS];
__device__ float g_rowinv[NROWS];

struct ProjArgs {
    const float* X[3];
    const float* W[3];
    const float* b[3];
    __half*      Y[3];
    float        scale[3];
};

#define LDMX4(R0,R1,R2,R3,addr) \
  asm volatile("ldmatrix.sync.aligned.m8n8.x4.shared.b16 {%0,%1,%2,%3}, [%4];" \
    : "=r"(R0),"=r"(R1),"=r"(R2),"=r"(R3) : "r"(addr))
#define LDMX4T(R0,R1,R2,R3,addr) \
  asm volatile("ldmatrix.sync.aligned.m8n8.x4.trans.shared.b16 {%0,%1,%2,%3}, [%4];" \
    : "=r"(R0),"=r"(R1),"=r"(R2),"=r"(R3) : "r"(addr))
#define MMA16816(C, A0,A1,A2,A3, B0,B1) \
  asm volatile("mma.sync.aligned.m16n8k16.row.col.f32.f16.f16.f32 " \
    "{%0,%1,%2,%3}, {%4,%5,%6,%7}, {%8,%9}, {%0,%1,%2,%3};" \
    : "+f"(C[0]),"+f"(C[1]),"+f"(C[2]),"+f"(C[3]) \
    : "r"(A0),"r"(A1),"r"(A2),"r"(A3), "r"(B0),"r"(B1))

__device__ __forceinline__ unsigned int smem_u32(const void* p) {
    return (unsigned int)__cvta_generic_to_shared(p);
}

// ---------------------------------------------------------------------------
// Fused projections: Y[z] = fp16((X[z] @ W[z] + b[z]) * scale[z]).
// 128x128 tile, 8x8 micro, fp32 math. grid (4, 64, 3), 256 threads.
// ---------------------------------------------------------------------------
__global__ void __launch_bounds__(256) proj128_kernel(ProjArgs args)
{
    const int z = blockIdx.z;
    const float* __restrict__ X    = args.X[z];
    const float* __restrict__ W    = args.W[z];
    const float* __restrict__ bias = args.b[z];
    __half* __restrict__ Y         = args.Y[z];
    const float qs                 = args.scale[z];

    __shared__ float As[16][132];
    __shared__ float Bs[16][128];

    const int tid = threadIdx.x;
    const int tx = tid & 15, ty = tid >> 4;
    const int bm = blockIdx.y * 128, bn = blockIdx.x * 128;

    const int arow = tid >> 2;
    const int akq  = (tid & 3) << 2;
    const int brow = tid >> 5;
    const int bcol = (tid & 31) << 2;

    float acc[8][8] = {};

    for (int k0 = 0; k0 < 512; k0 += 16) {
        float4 a0 = *(const float4*)&X[(size_t)(bm + arow)      * 512 + k0 + akq];
        float4 a1 = *(const float4*)&X[(size_t)(bm + arow + 64) * 512 + k0 + akq];
        float4 b0 = *(const float4*)&W[(size_t)(k0 + brow)      * 512 + bn + bcol];
        float4 b1 = *(const float4*)&W[(size_t)(k0 + brow + 8)  * 512 + bn + bcol];
        __syncthreads();
        As[akq+0][arow] = a0.x; As[akq+1][arow] = a0.y;
        As[akq+2][arow] = a0.z; As[akq+3][arow] = a0.w;
        As[akq+0][arow+64] = a1.x; As[akq+1][arow+64] = a1.y;
        As[akq+2][arow+64] = a1.z; As[akq+3][arow+64] = a1.w;
        *(float4*)&Bs[brow][bcol]   = b0;
        *(float4*)&Bs[brow+8][bcol] = b1;
        __syncthreads();
        #pragma unroll
        for (int k = 0; k < 16; k++) {
            float4 av0 = *(float4*)&As[k][ty*4];
            float4 av1 = *(float4*)&As[k][64 + ty*4];
            float4 bv0 = *(float4*)&Bs[k][tx*4];
            float4 bv1 = *(float4*)&Bs[k][64 + tx*4];
            float ar[8] = {av0.x,av0.y,av0.z,av0.w,av1.x,av1.y,av1.z,av1.w};
            float br[8] = {bv0.x,bv0.y,bv0.z,bv0.w,bv1.x,bv1.y,bv1.z,bv1.w};
            #pragma unroll
            for (int i = 0; i < 8; i++)
                #pragma unroll
                for (int j = 0; j < 8; j++)
                    acc[i][j] += ar[i] * br[j];
        }
    }

    #pragma unroll
    for (int i = 0; i < 8; i++) {
        int r = bm + ((i < 4) ? (ty*4 + i) : (64 + ty*4 + i - 4));
        #pragma unroll
        for (int jq = 0; jq < 2; jq++) {
            int c = bn + jq*64 + tx*4;
            __half2 h0 = __floats2half2_rn((acc[i][jq*4+0] + bias[c+0]) * qs,
                                           (acc[i][jq*4+1] + bias[c+1]) * qs);
            __half2 h1 = __floats2half2_rn((acc[i][jq*4+2] + bias[c+2]) * qs,
                                           (acc[i][jq*4+3] + bias[c+3]) * qs);
            uint2 pk;
            pk.x = *(unsigned int*)&h0;
            pk.y = *(unsigned int*)&h1;
            *(uint2*)&Y[(size_t)r * 512 + c] = pk;
        }
    }
}

// ---------------------------------------------------------------------------
// Scores via HMMA: S[128,128] tile = Qh[128,64] @ Kh[128,64]^T (scale folded
// into Qh).  Writes raw S fp32 + per-(row, 64-wide warp tile) softmax stats.
// grid (16, 16, 32), 256 threads = 8 warps (4 m x 2 n), warp tile 32x64.
// ---------------------------------------------------------------------------
__global__ void __launch_bounds__(256) scores_tc_kernel(float* __restrict__ attn)
{
    __shared__ uint4 Qs[128*8];
    __shared__ uint4 Ks[128*8];

    const int tid = threadIdx.x;
    const int lane = tid & 31, w = tid >> 5;
    const int bh = blockIdx.z, b = bh >> 3, h = bh & 7;
    const int bm = blockIdx.y * 128, bn = blockIdx.x * 128;
    const __half* __restrict__ Qg = g_Qh + (size_t)b * LL * DM + h * DK;
    const __half* __restrict__ Kg = g_Kh + (size_t)b * LL * DM + h * DK;

    // load 128x64 half tiles (1024 16B chunks each), XOR-8 swizzle
    for (int ci = tid; ci < 1024; ci += 256) {
        int r = ci >> 3, c = ci & 7;
        Qs[r*8 + (c ^ (r & 7))] = *(const uint4*)&Qg[(size_t)(bm + r) * DM + c*8];
        Ks[r*8 + (c ^ (r & 7))] = *(const uint4*)&Kg[(size_t)(bn + r) * DM + c*8];
    }
    __syncthreads();

    const int wm = (w & 3) * 32, wn = (w >> 2) * 64;
    const unsigned int qbase = smem_u32(Qs), kbase = smem_u32(Ks);

    float acc[2][8][4] = {};

    #pragma unroll
    for (int ks = 0; ks < 4; ks++) {
        unsigned int a[2][4];
        #pragma unroll
        for (int t = 0; t < 2; t++) {
            int r = wm + t*16 + (lane & 15);
            int c = (ks*2 + (lane >> 4)) ^ (r & 7);
            LDMX4(a[t][0], a[t][1], a[t][2], a[t][3], qbase + (r*8 + c)*16);
        }
        #pragma unroll
        for (int u2 = 0; u2 < 4; u2++) {
            unsigned int bf[4];
            int r = wn + u2*16 + (lane & 7) + ((lane >> 4) << 3);
            int c = (ks*2 + ((lane >> 3) & 1)) ^ (r & 7);
            LDMX4(bf[0], bf[1], bf[2], bf[3], kbase + (r*8 + c)*16);
            #pragma unroll
            for (int t = 0; t < 2; t++) {
                MMA16816(acc[t][u2*2],   a[t][0],a[t][1],a[t][2],a[t][3], bf[0], bf[1]);
                MMA16816(acc[t][u2*2+1], a[t][0],a[t][1],a[t][2],a[t][3], bf[2], bf[3]);
            }
        }
    }

    float* S = attn + (size_t)bh * LL * LL;
    const int ct = blockIdx.x * 2 + (w >> 2);
    #pragma unroll
    for (int t = 0; t < 2; t++) {
        #pragma unroll
        for (int hh = 0; hh < 2; hh++) {
            int r = bm + wm + t*16 + (lane >> 2) + hh*8;
            float mx = -3.4e38f;
            #pragma unroll
            for (int u = 0; u < 8; u++) {
                float2 v = make_float2(acc[t][u][hh*2], acc[t][u][hh*2+1]);
                *(float2*)&S[(size_t)r * LL + bn + wn + u*8 + (lane & 3)*2] = v;
                mx = fmaxf(mx, fmaxf(v.x, v.y));
            }
            mx = fmaxf(mx, __shfl_xor_sync(0xffffffffu, mx, 1));
            mx = fmaxf(mx, __shfl_xor_sync(0xffffffffu, mx, 2));
            float sm = 0.f;
            #pragma unroll
            for (int u = 0; u < 8; u++)
                sm += __expf(acc[t][u][hh*2] - mx) + __expf(acc[t][u][hh*2+1] - mx);
            sm += __shfl_xor_sync(0xffffffffu, sm, 1);
            sm += __shfl_xor_sync(0xffffffffu, sm, 2);
            if ((lane & 3) == 0) {
                size_t idx = (size_t)(bh * LL + r) * NCT + ct;
                g_mpart[idx] = mx;
                g_spart[idx] = sm;
            }
        }
    }
}

// ---------------------------------------------------------------------------
// Combine partial stats -> per-row max and 1/sum.
// ---------------------------------------------------------------------------
__global__ void __launch_bounds__(256) combine_kernel()
{
    int row = blockIdx.x * 256 + threadIdx.x;
    const float* mp = &g_mpart[(size_t)row * NCT];
    const float* sp = &g_spart[(size_t)row * NCT];
    float m = mp[0];
    #pragma unroll
    for (int t = 1; t < NCT; t++) m = fmaxf(m, mp[t]);
    float s = 0.f;
    #pragma unroll
    for (int t = 0; t < NCT; t++) s += sp[t] * __expf(mp[t] - m);
    g_rowm[row] = m;
    g_rowinv[row] = 1.0f / s;
}

// ---------------------------------------------------------------------------
// av: read raw S, P = exp(S-m)*inv -> write P (in place) + fp16 smem,
// O = P @ V via HMMA (V consumed with ldmatrix.trans).
// Block: 128 rows x DK=64, k-chunks of 64.  grid (16, 32), 256 thr = 8 warps,
// warp tile 16 x 64.
// ---------------------------------------------------------------------------
__global__ void __launch_bounds__(256) av_tc_kernel(float* __restrict__ attn,
                                                    float* __restrict__ out)
{
    __shared__ uint4 Ps[128*8];
    __shared__ uint4 Vs[64*8];

    const int tid = threadIdx.x;
    const int lane = tid & 31, w = tid >> 5;
    const int bh = blockIdx.y, b = bh >> 3, h = bh & 7;
    const int bm = blockIdx.x * 128;
    float* __restrict__ S = attn + (size_t)bh * LL * LL;
    const __half* __restrict__ Vg = g_Vh + (size_t)b * LL * DM + h * DK;

    const int prow = tid >> 1;           // 0..127
    const int pc0  = (tid & 1) * 4;      // chunk 0..3 or 4..7
    const float m_s = g_rowm[bh * LL + bm + prow];
    const float i_s = g_rowinv[bh * LL + bm + prow];

    const unsigned int pbase = smem_u32(Ps), vbase = smem_u32(Vs);
    const int wm = w * 16;

    float acc[8][4] = {};

    for (int k0 = 0; k0 < LL; k0 += 64) {
        __syncthreads();   // previous iteration's ldmatrix reads complete
        // P generation: row prow, 32 contiguous floats
        #pragma unroll
        for (int c = 0; c < 4; c++) {
            size_t gidx = (size_t)(bm + prow) * LL + k0 + (pc0 + c) * 8;
            float4 v0 = *(const float4*)&S[gidx];
            float4 v1 = *(const float4*)&S[gidx + 4];
            v0.x = __expf(v0.x - m_s) * i_s; v0.y = __expf(v0.y - m_s) * i_s;
            v0.z = __expf(v0.z - m_s) * i_s; v0.w = __expf(v0.w - m_s) * i_s;
            v1.x = __expf(v1.x - m_s) * i_s; v1.y = __expf(v1.y - m_s) * i_s;
            v1.z = __expf(v1.z - m_s) * i_s; v1.w = __expf(v1.w - m_s) * i_s;
            *(float4*)&S[gidx]     = v0;
            *(float4*)&S[gidx + 4] = v1;
            __half2 h0 = __floats2half2_rn(v0.x, v0.y);
            __half2 h1 = __floats2half2_rn(v0.z, v0.w);
            __half2 h2 = __floats2half2_rn(v1.x, v1.y);
            __half2 h3 = __floats2half2_rn(v1.z, v1.w);
            uint4 pk;
            pk.x = *(unsigned int*)&h0; pk.y = *(unsigned int*)&h1;
            pk.z = *(unsigned int*)&h2; pk.w = *(unsigned int*)&h3;
            Ps[prow*8 + ((pc0 + c) ^ (prow & 7))] = pk;
        }
        // V chunk: 64 rows x 8 chunks
        #pragma unroll
        for (int ci = tid; ci < 512; ci += 256) {
            int r = ci >> 3, c = ci & 7;
            Vs[r*8 + (c ^ (r & 7))] = *(const uint4*)&Vg[(size_t)(k0 + r) * DM + c*8];
        }
        __syncthreads();

        #pragma unroll
        for (int ks = 0; ks < 4; ks++) {
            unsigned int a[4];
            {
                int r = wm + (lane & 15);
                int c = (ks*2 + (lane >> 4)) ^ (r & 7);
                LDMX4(a[0], a[1], a[2], a[3], pbase + (r*8 + c)*16);
            }
            #pragma unroll
            for (int u2 = 0; u2 < 4; u2++) {
                unsigned int bf[4];
                int r = ks*16 + (lane & 7) + (((lane >> 3) & 1) << 3);
                int c = (u2*2 + ((lane >> 4) & 1)) ^ (r & 7);
                LDMX4T(bf[0], bf[1], bf[2], bf[3], vbase + (r*8 + c)*16);
                MMA16816(acc[u2*2],   a[0],a[1],a[2],a[3], bf[0], bf[1]);
                MMA16816(acc[u2*2+1], a[0],a[1],a[2],a[3], bf[2], bf[3]);
            }
        }
    }

    #pragma unroll
    for (int u = 0; u < 8; u++) {
        #pragma unroll
        for (int hh = 0; hh < 2; hh++) {
            int r = bm + wm + (lane >> 2) + hh*8;
            float2 v = make_float2(acc[u][hh*2], acc[u][hh*2+1]);
            *(float2*)&out[(size_t)(b * LL + r) * DM + h * DK + u*8 + (lane & 3)*2] = v;
        }
    }
}

// ---------------------------------------------------------------------------
extern "C" void kernel_launch(void* const* d_in, const int* in_sizes, int n_in,
                              void* d_out, int out_size)
{
    const float* q  = (const float*)d_in[0];
    const float* k  = (const float*)d_in[1];
    const float* v  = (const float*)d_in[2];
    const float* Wq = (const float*)d_in[3];
    const float* bq = (const float*)d_in[4];
    const float* Wk = (const float*)d_in[5];
    const float* bk = (const float*)d_in[6];
    const float* Wv = (const float*)d_in[7];
    const float* bv = (const float*)d_in[8];

    float* out  = (float*)d_out;
    float* attn = out + OUT_ELEMS;

    __half *gQ, *gK, *gV;
    cudaGetSymbolAddress((void**)&gQ, g_Qh);
    cudaGetSymbolAddress((void**)&gK, g_Kh);
    cudaGetSymbolAddress((void**)&gV, g_Vh);

    ProjArgs pa;
    pa.X[0] = q;  pa.X[1] = k;  pa.X[2] = v;
    pa.W[0] = Wq; pa.W[1] = Wk; pa.W[2] = Wv;
    pa.b[0] = bq; pa.b[1] = bk; pa.b[2] = bv;
    pa.Y[0] = gQ; pa.Y[1] = gK; pa.Y[2] = gV;
    pa.scale[0] = 0.125f; pa.scale[1] = 1.0f; pa.scale[2] = 1.0f;

    dim3 blk(256);
    proj128_kernel<<<dim3(4, 64, 3), blk>>>(pa);
    scores_tc_kernel<<<dim3(16, 16, 32), blk>>>(attn);
    combine_kernel<<<dim3(NROWS / 256), blk>>>();
    av_tc_kernel<<<dim3(16, 32), blk>>>(attn, out);
}

// round 8
// speedup vs baseline: 1.6793x; 1.6793x over previous
#include <cuda_runtime.h>
#include <cuda_fp16.h>
#include <cstdint>

#define DM 512
#define NH 8
#define DK 64
#define BB 4
#define LL 2048
#define MROWS (BB*LL)                    // 8192
#define OUT_ELEMS ((size_t)MROWS*DM)     // 4,194,304
#define NROWS (BB*NH*LL)                 // 65536 softmax rows
#define NCT 32                           // 2048 / 64-wide stat tiles

__device__ __half g_Qh[MROWS*DM];   // Q * 0.125 in fp16
__device__ __half g_Kh[MROWS*DM];
__device__ __half g_Vh[MROWS*DM];
__device__ float g_mpart[(size_t)NROWS*NCT];
__device__ float g_spart[(size_t)NROWS*NCT];
__device__ float g_rowm[NROWS];
__device__ float g_rowinv[NROWS];

struct ProjArgs {
    const float* X[3];
    const float* W[3];
    const float* b[3];
    __half*      Y[3];
    float        scale[3];
};

#define LDMX4(R0,R1,R2,R3,addr) \
  asm volatile("ldmatrix.sync.aligned.m8n8.x4.shared.b16 {%0,%1,%2,%3}, [%4];" \
    : "=r"(R0),"=r"(R1),"=r"(R2),"=r"(R3) : "r"(addr))
#define LDMX4T(R0,R1,R2,R3,addr) \
  asm volatile("ldmatrix.sync.aligned.m8n8.x4.trans.shared.b16 {%0,%1,%2,%3}, [%4];" \
    : "=r"(R0),"=r"(R1),"=r"(R2),"=r"(R3) : "r"(addr))
#define MMA16816(C, A0,A1,A2,A3, B0,B1) \
  asm volatile("mma.sync.aligned.m16n8k16.row.col.f32.f16.f16.f32 " \
    "{%0,%1,%2,%3}, {%4,%5,%6,%7}, {%8,%9}, {%0,%1,%2,%3};" \
    : "+f"(C[0]),"+f"(C[1]),"+f"(C[2]),"+f"(C[3]) \
    : "r"(A0),"r"(A1),"r"(A2),"r"(A3), "r"(B0),"r"(B1))

__device__ __forceinline__ unsigned int smem_u32(const void* p) {
    return (unsigned int)__cvta_generic_to_shared(p);
}

// ---------------------------------------------------------------------------
// Fused projections: Y[z] = fp16((X[z] @ W[z] + b[z]) * scale[z]).
// 128x128 tile, 8x8 micro, fp32 math. grid (4, 64, 3), 256 threads.
// ---------------------------------------------------------------------------
__global__ void __launch_bounds__(256) proj128_kernel(ProjArgs args)
{
    const int z = blockIdx.z;
    const float* __restrict__ X    = args.X[z];
    const float* __restrict__ W    = args.W[z];
    const float* __restrict__ bias = args.b[z];
    __half* __restrict__ Y         = args.Y[z];
    const float qs                 = args.scale[z];

    __shared__ float As[16][132];
    __shared__ float Bs[16][128];

    const int tid = threadIdx.x;
    const int tx = tid & 15, ty = tid >> 4;
    const int bm = blockIdx.y * 128, bn = blockIdx.x * 128;

    const int arow = tid >> 2;
    const int akq  = (tid & 3) << 2;
    const int brow = tid >> 5;
    const int bcol = (tid & 31) << 2;

    float acc[8][8] = {};

    for (int k0 = 0; k0 < 512; k0 += 16) {
        float4 a0 = *(const float4*)&X[(size_t)(bm + arow)      * 512 + k0 + akq];
        float4 a1 = *(const float4*)&X[(size_t)(bm + arow + 64) * 512 + k0 + akq];
        float4 b0 = *(const float4*)&W[(size_t)(k0 + brow)      * 512 + bn + bcol];
        float4 b1 = *(const float4*)&W[(size_t)(k0 + brow + 8)  * 512 + bn + bcol];
        __syncthreads();
        As[akq+0][arow] = a0.x; As[akq+1][arow] = a0.y;
        As[akq+2][arow] = a0.z; As[akq+3][arow] = a0.w;
        As[akq+0][arow+64] = a1.x; As[akq+1][arow+64] = a1.y;
        As[akq+2][arow+64] = a1.z; As[akq+3][arow+64] = a1.w;
        *(float4*)&Bs[brow][bcol]   = b0;
        *(float4*)&Bs[brow+8][bcol] = b1;
        __syncthreads();
        #pragma unroll
        for (int k = 0; k < 16; k++) {
            float4 av0 = *(float4*)&As[k][ty*4];
            float4 av1 = *(float4*)&As[k][64 + ty*4];
            float4 bv0 = *(float4*)&Bs[k][tx*4];
            float4 bv1 = *(float4*)&Bs[k][64 + tx*4];
            float ar[8] = {av0.x,av0.y,av0.z,av0.w,av1.x,av1.y,av1.z,av1.w};
            float br[8] = {bv0.x,bv0.y,bv0.z,bv0.w,bv1.x,bv1.y,bv1.z,bv1.w};
            #pragma unroll
            for (int i = 0; i < 8; i++)
                #pragma unroll
                for (int j = 0; j < 8; j++)
                    acc[i][j] += ar[i] * br[j];
        }
    }

    #pragma unroll
    for (int i = 0; i < 8; i++) {
        int r = bm + ((i < 4) ? (ty*4 + i) : (64 + ty*4 + i - 4));
        #pragma unroll
        for (int jq = 0; jq < 2; jq++) {
            int c = bn + jq*64 + tx*4;
            __half2 h0 = __floats2half2_rn((acc[i][jq*4+0] + bias[c+0]) * qs,
                                           (acc[i][jq*4+1] + bias[c+1]) * qs);
            __half2 h1 = __floats2half2_rn((acc[i][jq*4+2] + bias[c+2]) * qs,
                                           (acc[i][jq*4+3] + bias[c+3]) * qs);
            uint2 pk;
            pk.x = *(unsigned int*)&h0;
            pk.y = *(unsigned int*)&h1;
            *(uint2*)&Y[(size_t)r * 512 + c] = pk;
        }
    }
}

// ---------------------------------------------------------------------------
// Scores via HMMA: S[128,128] tile = Qh[128,64] @ Kh[128,64]^T (scale folded
// into Qh).  Writes raw S fp32 + per-(row, 64-wide warp tile) softmax stats.
// grid (16, 16, 32), 256 threads = 8 warps (4 m x 2 n), warp tile 32x64.
// ---------------------------------------------------------------------------
__global__ void __launch_bounds__(256) scores_tc_kernel(float* __restrict__ attn)
{
    __shared__ uint4 Qs[128*8];
    __shared__ uint4 Ks[128*8];

    const int tid = threadIdx.x;
    const int lane = tid & 31, w = tid >> 5;
    const int bh = blockIdx.z, b = bh >> 3, h = bh & 7;
    const int bm = blockIdx.y * 128, bn = blockIdx.x * 128;
    const __half* __restrict__ Qg = g_Qh + (size_t)b * LL * DM + h * DK;
    const __half* __restrict__ Kg = g_Kh + (size_t)b * LL * DM + h * DK;

    for (int ci = tid; ci < 1024; ci += 256) {
        int r = ci >> 3, c = ci & 7;
        Qs[r*8 + (c ^ (r & 7))] = *(const uint4*)&Qg[(size_t)(bm + r) * DM + c*8];
        Ks[r*8 + (c ^ (r & 7))] = *(const uint4*)&Kg[(size_t)(bn + r) * DM + c*8];
    }
    __syncthreads();

    const int wm = (w & 3) * 32, wn = (w >> 2) * 64;
    const unsigned int qbase = smem_u32(Qs), kbase = smem_u32(Ks);

    float acc[2][8][4] = {};

    #pragma unroll
    for (int ks = 0; ks < 4; ks++) {
        unsigned int a[2][4];
        #pragma unroll
        for (int t = 0; t < 2; t++) {
            int r = wm + t*16 + (lane & 15);
            int c = (ks*2 + (lane >> 4)) ^ (r & 7);
            LDMX4(a[t][0], a[t][1], a[t][2], a[t][3], qbase + (r*8 + c)*16);
        }
        #pragma unroll
        for (int u2 = 0; u2 < 4; u2++) {
            unsigned int bf[4];
            int r = wn + u2*16 + (lane & 7) + ((lane >> 4) << 3);
            int c = (ks*2 + ((lane >> 3) & 1)) ^ (r & 7);
            LDMX4(bf[0], bf[1], bf[2], bf[3], kbase + (r*8 + c)*16);
            #pragma unroll
            for (int t = 0; t < 2; t++) {
                MMA16816(acc[t][u2*2],   a[t][0],a[t][1],a[t][2],a[t][3], bf[0], bf[1]);
                MMA16816(acc[t][u2*2+1], a[t][0],a[t][1],a[t][2],a[t][3], bf[2], bf[3]);
            }
        }
    }

    float* S = attn + (size_t)bh * LL * LL;
    const int ct = blockIdx.x * 2 + (w >> 2);
    #pragma unroll
    for (int t = 0; t < 2; t++) {
        #pragma unroll
        for (int hh = 0; hh < 2; hh++) {
            int r = bm + wm + t*16 + (lane >> 2) + hh*8;
            float mx = -3.4e38f;
            #pragma unroll
            for (int u = 0; u < 8; u++) {
                float2 v = make_float2(acc[t][u][hh*2], acc[t][u][hh*2+1]);
                *(float2*)&S[(size_t)r * LL + bn + wn + u*8 + (lane & 3)*2] = v;
                mx = fmaxf(mx, fmaxf(v.x, v.y));
            }
            mx = fmaxf(mx, __shfl_xor_sync(0xffffffffu, mx, 1));
            mx = fmaxf(mx, __shfl_xor_sync(0xffffffffu, mx, 2));
            float sm = 0.f;
            #pragma unroll
            for (int u = 0; u < 8; u++)
                sm += __expf(acc[t][u][hh*2] - mx) + __expf(acc[t][u][hh*2+1] - mx);
            sm += __shfl_xor_sync(0xffffffffu, sm, 1);
            sm += __shfl_xor_sync(0xffffffffu, sm, 2);
            if ((lane & 3) == 0) {
                size_t idx = (size_t)(bh * LL + r) * NCT + ct;
                g_mpart[idx] = mx;
                g_spart[idx] = sm;
            }
        }
    }
}

// ---------------------------------------------------------------------------
// Combine partial stats -> per-row max and 1/sum.
// ---------------------------------------------------------------------------
__global__ void __launch_bounds__(256) combine_kernel()
{
    int row = blockIdx.x * 256 + threadIdx.x;
    const float* mp = &g_mpart[(size_t)row * NCT];
    const float* sp = &g_spart[(size_t)row * NCT];
    float m = mp[0];
    #pragma unroll
    for (int t = 1; t < NCT; t++) m = fmaxf(m, mp[t]);
    float s = 0.f;
    #pragma unroll
    for (int t = 0; t < NCT; t++) s += sp[t] * __expf(mp[t] - m);
    g_rowm[row] = m;
    g_rowinv[row] = 1.0f / s;
}

// ---------------------------------------------------------------------------
// av v2: BM=64, register double-buffered S/V prefetch overlapping MMA.
// grid (32, 32), 256 thr = 8 warps, warp tile 16 x 32.
// Per iter: regs hold chunk k; store->smem; sync; prefetch k+1; MMA; sync.
// ---------------------------------------------------------------------------
__global__ void __launch_bounds__(256) av_tc_kernel(float* __restrict__ attn,
                                                    float* __restrict__ out)
{
    __shared__ uint4 Ps[64*8];
    __shared__ uint4 Vs[64*8];

    const int tid = threadIdx.x;
    const int lane = tid & 31, w = tid >> 5;
    const int bh = blockIdx.y, b = bh >> 3, h = bh & 7;
    const int bm = blockIdx.x * 64;
    float* __restrict__ S = attn + (size_t)bh * LL * LL;
    const __half* __restrict__ Vg = g_Vh + (size_t)b * LL * DM + h * DK;

    const int srow = tid >> 2;           // 0..63
    const int scol = (tid & 3) * 16;     // 0,16,32,48
    const int vrow = tid >> 2;           // 0..63 (reuse) -> 2 chunks per thread
    const int vc2  = (tid & 3) * 2;      // chunk pair 0..7

    const float m_s = g_rowm[bh * LL + bm + srow];
    const float i_s = g_rowinv[bh * LL + bm + srow];

    const unsigned int pbase = smem_u32(Ps), vbase = smem_u32(Vs);
    const int wm = (w & 3) * 16, wn = (w >> 2) * 32;

    float acc[4][4] = {};

    float4 rs[2][4];
    uint4  rv[2][2];

    // prologue: load chunk 0
    {
        const float* Srow = &S[(size_t)(bm + srow) * LL + scol];
        #pragma unroll
        for (int q = 0; q < 4; q++) rs[0][q] = *(const float4*)&Srow[q*4];
        #pragma unroll
        for (int q = 0; q < 2; q++)
            rv[0][q] = *(const uint4*)&Vg[(size_t)vrow * DM + (vc2 + q)*8];
    }

    int cur = 0;
    for (int k0 = 0; k0 < LL; k0 += 64) {
        // normalize chunk in registers; write P back to gmem (fire-and-forget)
        uint4 pk[2];
        #pragma unroll
        for (int j = 0; j < 2; j++) {
            float4 v0 = rs[cur][j*2], v1 = rs[cur][j*2+1];
            v0.x = __expf(v0.x - m_s) * i_s; v0.y = __expf(v0.y - m_s) * i_s;
            v0.z = __expf(v0.z - m_s) * i_s; v0.w = __expf(v0.w - m_s) * i_s;
            v1.x = __expf(v1.x - m_s) * i_s; v1.y = __expf(v1.y - m_s) * i_s;
            v1.z = __expf(v1.z - m_s) * i_s; v1.w = __expf(v1.w - m_s) * i_s;
            size_t gidx = (size_t)(bm + srow) * LL + k0 + scol + j*8;
            *(float4*)&S[gidx]     = v0;
            *(float4*)&S[gidx + 4] = v1;
            __half2 h0 = __floats2half2_rn(v0.x, v0.y);
            __half2 h1 = __floats2half2_rn(v0.z, v0.w);
            __half2 h2 = __floats2half2_rn(v1.x, v1.y);
            __half2 h3 = __floats2half2_rn(v1.z, v1.w);
            pk[j].x = *(unsigned int*)&h0; pk[j].y = *(unsigned int*)&h1;
            pk[j].z = *(unsigned int*)&h2; pk[j].w = *(unsigned int*)&h3;
        }
        // smem population
        #pragma unroll
        for (int j = 0; j < 2; j++) {
            int c = (tid & 3)*2 + j;
            Ps[srow*8 + (c ^ (srow & 7))] = pk[j];
        }
        #pragma unroll
        for (int q = 0; q < 2; q++) {
            int c = vc2 + q;
            Vs[vrow*8 + (c ^ (vrow & 7))] = rv[cur][q];
        }
        __syncthreads();

        // prefetch next chunk while MMA runs
        int nxt = cur ^ 1;
        if (k0 + 64 < LL) {
            const float* Srow = &S[(size_t)(bm + srow) * LL + (k0 + 64) + scol];
            #pragma unroll
            for (int q = 0; q < 4; q++) rs[nxt][q] = *(const float4*)&Srow[q*4];
            #pragma unroll
            for (int q = 0; q < 2; q++)
                rv[nxt][q] = *(const uint4*)&Vg[(size_t)(k0 + 64 + vrow) * DM + (vc2 + q)*8];
        }

        // MMA on smem chunk
        #pragma unroll
        for (int ks = 0; ks < 4; ks++) {
            unsigned int a[4];
            {
                int r = wm + (lane & 15);
                int c = (ks*2 + (lane >> 4)) ^ (r & 7);
                LDMX4(a[0], a[1], a[2], a[3], pbase + (r*8 + c)*16);
            }
            #pragma unroll
            for (int u2 = 0; u2 < 2; u2++) {
                unsigned int bf[4];
                int r = ks*16 + (lane & 7) + (((lane >> 3) & 1) << 3);
                int c = ((wn >> 3) + u2*2 + ((lane >> 4) & 1)) ^ (r & 7);
                LDMX4T(bf[0], bf[1], bf[2], bf[3], vbase + (r*8 + c)*16);
                MMA16816(acc[u2*2],   a[0],a[1],a[2],a[3], bf[0], bf[1]);
                MMA16816(acc[u2*2+1], a[0],a[1],a[2],a[3], bf[2], bf[3]);
            }
        }
        __syncthreads();
        cur = nxt;
    }

    #pragma unroll
    for (int u = 0; u < 4; u++) {
        #pragma unroll
        for (int hh = 0; hh < 2; hh++) {
            int r = bm + wm + (lane >> 2) + hh*8;
            float2 v = make_float2(acc[u][hh*2], acc[u][hh*2+1]);
            *(float2*)&out[(size_t)(b * LL + r) * DM + h * DK + wn + u*8 + (lane & 3)*2] = v;
        }
    }
}

// ---------------------------------------------------------------------------
extern "C" void kernel_launch(void* const* d_in, const int* in_sizes, int n_in,
                              void* d_out, int out_size)
{
    const float* q  = (const float*)d_in[0];
    const float* k  = (const float*)d_in[1];
    const float* v  = (const float*)d_in[2];
    const float* Wq = (const float*)d_in[3];
    const float* bq = (const float*)d_in[4];
    const float* Wk = (const float*)d_in[5];
    const float* bk = (const float*)d_in[6];
    const float* Wv = (const float*)d_in[7];
    const float* bv = (const float*)d_in[8];

    float* out  = (float*)d_out;
    float* attn = out + OUT_ELEMS;

    __half *gQ, *gK, *gV;
    cudaGetSymbolAddress((void**)&gQ, g_Qh);
    cudaGetSymbolAddress((void**)&gK, g_Kh);
    cudaGetSymbolAddress((void**)&gV, g_Vh);

    ProjArgs pa;
    pa.X[0] = q;  pa.X[1] = k;  pa.X[2] = v;
    pa.W[0] = Wq; pa.W[1] = Wk; pa.W[2] = Wv;
    pa.b[0] = bq; pa.b[1] = bk; pa.b[2] = bv;
    pa.Y[0] = gQ; pa.Y[1] = gK; pa.Y[2] = gV;
    pa.scale[0] = 0.125f; pa.scale[1] = 1.0f; pa.scale[2] = 1.0f;

    dim3 blk(256);
    proj128_kernel<<<dim3(4, 64, 3), blk>>>(pa);
    scores_tc_kernel<<<dim3(16, 16, 32), blk>>>(attn);
    combine_kernel<<<dim3(NROWS / 256), blk>>>();
    av_tc_kernel<<<dim3(32, 32), blk>>>(attn, out);
}